// round 11
// baseline (speedup 1.0000x reference)
#include <cuda_runtime.h>
#include <cuda_bf16.h>

#define NKC 5000
#define BB  512
#define TT  100
#define THREADS 256
#define TBL_SLICE 10          // table entries per solve block (512*10 >= 5000)
#define NCOPY 128             // copy blocks; 4 rows each
#define GRID (BB + NCOPY)

__device__ float  g_c4[NKC];          // sigmoid(logits[:,4]) — default state
__device__ float4 g_p4[NKC];          // sigmoid(logits[:,0..3])
__device__ int    g_ready;            // solve blocks that published table slice
__device__ int    g_done;             // blocks finished (reset)
__device__ volatile int g_flag[BB];   // per-batch: solve results staged
__device__ int    g_pidx[BB][TT];     // patch index (-1 = none)
__device__ float  g_pval[BB][TT];     // patch value

__device__ __forceinline__ float sigmoidf(float x) {
    return 1.0f / (1.0f + __expf(-x));
}

__global__ __launch_bounds__(THREADS, 4)
void fused_kernel(const int* __restrict__ prev_kc,
                  const int* __restrict__ curr_kc,
                  const int* __restrict__ prev_corr,
                  const float* __restrict__ logits,
                  float* __restrict__ out)
{
    const int tid = threadIdx.x;

    if (blockIdx.x < BB) {
        // ====================== SOLVE BLOCK (bids 0..511, wave-1) ======================
        __shared__ int   sPK[TT];
        __shared__ int   sPW[TT];
        __shared__ float sVal[TT];
        __shared__ int   sNotLast[TT];
        __shared__ int   sMaxD;

        const int b = blockIdx.x;

        // phase 0: warp-4 lanes build table slice & arrive; warps 0-3 load indices
        if (tid >= 128 && tid < 128 + TBL_SLICE) {
            const int k = b * TBL_SLICE + (tid - 128);
            if (k < NKC) {
                const float s0 = sigmoidf(logits[k * 5 + 0]);
                const float s1 = sigmoidf(logits[k * 5 + 1]);
                const float s2 = sigmoidf(logits[k * 5 + 2]);
                const float s3 = sigmoidf(logits[k * 5 + 3]);
                const float s4 = sigmoidf(logits[k * 5 + 4]);
                g_p4[k] = make_float4(s0, s1, s2, s3);
                g_c4[k] = s4;
            }
            __threadfence();
        }
        if (tid >= 128 && tid < 160) {
            __syncwarp();
            if (tid == 128) atomicAdd(&g_ready, 1);
        }

        int pk = -1, ck = -1, c = 0;
        if (tid == 0) sMaxD = 0;
        if (tid < TT) {
            ck = curr_kc[b * TT + tid];
            pk = prev_kc[b * TT + tid];
            c  = prev_corr[b * TT + tid];
            sPK[tid]      = (tid >= 1) ? pk : -9;
            sNotLast[tid] = 0;
        }
        __syncthreads();

        // predecessor-only dependency scan
        int pw = -1, w = -1;
        if (tid < TT) {
            const int4* sp4 = (const int4*)sPK;
            const int jmax = tid >> 2;
            for (int j = 0; j <= jmax; j++) {
                const int4 v = sp4[j];
                const int s0 = 4 * j;
                if (v.x == pk && s0     < tid) pw = s0;
                if (v.y == pk && s0 + 1 < tid) pw = s0 + 1;
                if (v.z == pk && s0 + 2 < tid) pw = s0 + 2;
                if (v.w == pk && s0 + 3 < tid) pw = s0 + 3;
                if (v.x == ck && s0     <= tid) w = s0;
                if (v.y == ck && s0 + 1 <= tid) w = s0 + 1;
                if (v.z == ck && s0 + 2 <= tid) w = s0 + 2;
                if (v.w == ck && s0 + 3 <= tid) w = s0 + 3;
            }
            sPW[tid] = pw;
            if (pw >= 0) sNotLast[pw] = 1;
        }
        __syncthreads();

        // chain depth
        int depth = 0;
        if (tid >= 1 && tid < TT) {
            int j = pw;
            while (j >= 0) { j = sPW[j]; depth++; }
            atomicMax(&sMaxD, depth);
        }

        // wait for full table
        if (tid == 0) {
            while (*(volatile int*)&g_ready < BB)
                __nanosleep(20);
            __threadfence();
        }
        __syncthreads();
        const int maxD = sMaxD;

        // table-dependent constants
        float A = 0.f, Bc = 0.f, P0 = 0.f, E = 0.f, F = 0.f, G = 0.f;
        float initSkill = 0.f, initCs = 0.f;
        if (tid < TT) {
            const float4 cp = g_p4[ck];
            G = cp.z;
            F = cp.w - cp.z;
            initCs = g_c4[ck];
            if (tid >= 1) {
                const float4 pp = g_p4[pk];
                A  = c ? pp.w : (1.0f - pp.w);
                Bc = c ? pp.z : (1.0f - pp.z);
                P0 = pp.x;
                E  = 1.0f - pp.y - pp.x;
                initSkill = g_c4[pk];
            }
        }

        // wavefront by depth
        float myVal = 0.f;
        for (int r = 0; r <= maxD; r++) {
            __syncthreads();
            if (tid >= 1 && tid < TT && depth == r) {
                const float skill = (r == 0) ? initSkill : sVal[pw];
                const float num   = A * skill;
                const float den   = fmaf(Bc, -skill, Bc) + num;
                const float filt  = __fdividef(num, den);
                myVal = fmaf(E, filt, P0);
                sVal[tid] = myVal;
            }
        }
        __syncthreads();

        // probs + stage patches
        if (tid < TT) {
            const float cs = (w < 0) ? initCs : sVal[w];
            out[b * TT + tid] = fmaf(F, cs, G);
            const bool isPatch = (tid >= 1) && !sNotLast[tid];
            g_pidx[b][tid] = isPatch ? pk : -1;
            g_pval[b][tid] = myVal;
        }
        __syncthreads();
        if (tid == 0) {
            __threadfence();
            g_flag[b] = 1;                    // publish: row b ready for copy block
        }
    } else {
        // ====================== COPY BLOCK (bids 512..639) ======================
        const int cb = blockIdx.x - BB;

        // wait for full table (needed for g_c4 stream)
        if (tid == 0) {
            while (*(volatile int*)&g_ready < BB)
                __nanosleep(20);
            __threadfence();
        }
        __syncthreads();

        for (int j = 0; j < BB / NCOPY; j++) {
            const int b = cb * (BB / NCOPY) + j;
            float* __restrict__ orow = out + (size_t)BB * TT + (size_t)b * NKC;

            // wait for this batch's solve results
            if (tid == 0) {
                while (g_flag[b] == 0)
                    __nanosleep(20);
                __threadfence();
            }
            __syncthreads();

            // stream default state row (loads batched, MLP=5)
            {
                const float4* __restrict__ src = (const float4*)g_c4;
                float4*       __restrict__ dst = (float4*)orow;
                float4 v[5];
                #pragma unroll
                for (int u = 0; u < 5; u++) {
                    const int i = tid + u * THREADS;
                    if (i < NKC / 4) v[u] = src[i];
                }
                #pragma unroll
                for (int u = 0; u < 5; u++) {
                    const int i = tid + u * THREADS;
                    if (i < NKC / 4) dst[i] = v[u];
                }
            }
            __syncthreads();                   // copy complete before patches

            // apply patches + reset flag for next replay
            if (tid < TT) {
                const int   idx = g_pidx[b][tid];
                const float val = g_pval[b][tid];
                if (idx >= 0) orow[idx] = val;
            }
            __syncthreads();
            if (tid == 0) g_flag[b] = 0;       // sole consumer resets
        }
    }

    // ---- counter reset for next graph replay ----
    if (tid == 0) {
        const int d = atomicAdd(&g_done, 1);
        if (d == GRID - 1) {                   // everyone past all spins
            g_ready = 0;
            g_done  = 0;
        }
    }
}

extern "C" void kernel_launch(void* const* d_in, const int* in_sizes, int n_in,
                              void* d_out, int out_size) {
    const int*   prev_kc   = (const int*)d_in[0];
    const int*   curr_kc   = (const int*)d_in[1];
    const int*   prev_corr = (const int*)d_in[2];
    const float* kc_logits = (const float*)d_in[3];
    float*       out       = (float*)d_out;

    fused_kernel<<<GRID, THREADS>>>(prev_kc, curr_kc, prev_corr, kc_logits, out);
}

// round 12
// speedup vs baseline: 1.2166x; 1.2166x over previous
#include <cuda_runtime.h>
#include <cuda_bf16.h>

#define NKC 5000
#define BB  512
#define TT  100
#define THREADS 512
#define QPB 4                  // batches per block
#define NBLK (BB / QPB)        // 128 blocks
#define TBL_SLICE 40           // table entries per block (128*40 >= 5000)

__device__ float  g_c4[NKC];   // sigmoid(logits[:,4]) — default state
__device__ float4 g_p4[NKC];   // sigmoid(logits[:,0..3])
__device__ int    g_ready;     // blocks that published their table slice
__device__ int    g_done;      // blocks finished (reset)

__device__ __forceinline__ float sigmoidf(float x) {
    return 1.0f / (1.0f + __expf(-x));
}

__global__ __launch_bounds__(THREADS, 1)
void fused_kernel(const int* __restrict__ prev_kc,
                  const int* __restrict__ curr_kc,
                  const int* __restrict__ prev_corr,
                  const float* __restrict__ logits,
                  float* __restrict__ out)
{
    __shared__ int   sPK[QPB][TT];
    __shared__ int   sPW[QPB][TT];
    __shared__ float sVal[QPB][TT];
    __shared__ int   sNotLast[QPB][TT];
    __shared__ int   sMaxD;

    const int bid = blockIdx.x;
    const int tid = threadIdx.x;
    const bool solver = (tid < QPB * TT);
    const int q = tid / TT;                 // sub-batch 0..3 (solver threads)
    const int t = tid - q * TT;             // step within batch

    // ---- phase 0a: warp 13 (tid 416-447) builds table slice & arrives ----
    if (tid >= 416 && tid < 448) {
        const int lane = tid - 416;
        int k = bid * TBL_SLICE + lane;
        #pragma unroll
        for (int rep = 0; rep < 2; rep++) {  // lanes 0-7 build a second entry
            if ((rep == 0 || lane < TBL_SLICE - 32) && k < NKC) {
                const float s0 = sigmoidf(logits[k * 5 + 0]);
                const float s1 = sigmoidf(logits[k * 5 + 1]);
                const float s2 = sigmoidf(logits[k * 5 + 2]);
                const float s3 = sigmoidf(logits[k * 5 + 3]);
                const float s4 = sigmoidf(logits[k * 5 + 4]);
                g_p4[k] = make_float4(s0, s1, s2, s3);
                g_c4[k] = s4;
            }
            k += 32;
        }
        __threadfence();
        __syncwarp();
        if (tid == 416)
            atomicAdd(&g_ready, 1);
    }

    // ---- phase 0b: coalesced index loads (threads 0-399) ----
    int pk = -1, ck = -1, c = 0;
    if (tid == 0) sMaxD = 0;
    if (solver) {
        const int gi = bid * (QPB * TT) + tid;   // fully coalesced
        ck = curr_kc[gi];
        pk = prev_kc[gi];
        c  = prev_corr[gi];
        sPK[q][t]      = (t >= 1) ? pk : -9;     // step 0 performs no update
        sNotLast[q][t] = 0;
    }
    __syncthreads();

    // ---- predecessor-only dependency scan (per sub-batch) ----
    int pw = -1;           // last s' <  t writing pk  (skill source)
    int w  = -1;           // last s' <= t writing ck  (probs source)
    if (solver) {
        const int4* sp4 = (const int4*)sPK[q];
        const int jmax = t >> 2;
        for (int j = 0; j <= jmax; j++) {
            const int4 v = sp4[j];
            const int s0 = 4 * j;
            if (v.x == pk && s0     < t) pw = s0;
            if (v.y == pk && s0 + 1 < t) pw = s0 + 1;
            if (v.z == pk && s0 + 2 < t) pw = s0 + 2;
            if (v.w == pk && s0 + 3 < t) pw = s0 + 3;
            if (v.x == ck && s0     <= t) w = s0;
            if (v.y == ck && s0 + 1 <= t) w = s0 + 1;
            if (v.z == ck && s0 + 2 <= t) w = s0 + 2;
            if (v.w == ck && s0 + 3 <= t) w = s0 + 3;
        }
        sPW[q][t] = pw;
        if (pw >= 0) sNotLast[q][pw] = 1;        // pw distinct per q -> plain store
    }
    __syncthreads();

    // ---- chain depth via pointer chase (depth ~1-4) ----
    int depth = 0;
    if (solver && t >= 1) {
        int j = pw;
        while (j >= 0) { j = sPW[q][j]; depth++; }
        atomicMax(&sMaxD, depth);
    }

    // ---- grid handshake: wait for all 128 table slices ----
    if (tid == 0) {
        while (*(volatile int*)&g_ready < NBLK)
            __nanosleep(20);
        __threadfence();
    }
    __syncthreads();                             // publishes sMaxD too
    const int maxD = sMaxD;

    // ---- table-dependent constants gather ----
    float A = 0.f, Bc = 0.f, P0 = 0.f, E = 0.f, F = 0.f, G = 0.f;
    float initSkill = 0.f, initCs = 0.f;
    if (solver) {
        const float4 cp = g_p4[ck];
        G = cp.z;
        F = cp.w - cp.z;
        initCs = g_c4[ck];
        if (t >= 1) {
            const float4 pp = g_p4[pk];
            A  = c ? pp.w : (1.0f - pp.w);       // p_out[:,1]
            Bc = c ? pp.z : (1.0f - pp.z);       // p_out[:,0]
            P0 = pp.x;
            E  = 1.0f - pp.y - pp.x;
            initSkill = g_c4[pk];
        }
    }

    // ---- wavefront by depth (4 sub-batches in lockstep) ----
    float myVal = 0.f;
    for (int r = 0; r <= maxD; r++) {
        __syncthreads();
        if (solver && t >= 1 && depth == r) {
            const float skill = (r == 0) ? initSkill : sVal[q][pw];
            const float num   = A * skill;
            const float den   = fmaf(Bc, -skill, Bc) + num;  // B*(1-skill)+A*skill
            const float filt  = __fdividef(num, den);
            myVal = fmaf(E, filt, P0);
            sVal[q][t] = myVal;
        }
    }
    __syncthreads();

    // ---- probs output (coalesced: out[bid*400 + tid]) ----
    if (solver) {
        const float cs = (w < 0) ? initCs : sVal[q][w];
        out[bid * (QPB * TT) + tid] = fmaf(F, cs, G);
    }

    // ---- bulk copy: 4 rows, all 512 threads, MLP=10 batched ----
    {
        const float4* __restrict__ src = (const float4*)g_c4;
        float4* __restrict__ dstBase =
            (float4*)(out + (size_t)BB * TT + (size_t)bid * QPB * NKC);
        const int ROWQ = NKC / 4;                // 1250 float4 per row
        float4 v[10];
        int   idx[10];
        #pragma unroll
        for (int u = 0; u < 10; u++) {
            const int i = tid + u * THREADS;     // 0..5119 over 4 rows
            idx[u] = i;
            if (i < QPB * ROWQ) {
                const int col = i % ROWQ;        // which element within a row
                v[u] = src[col];
            }
        }
        #pragma unroll
        for (int u = 0; u < 10; u++) {
            const int i = idx[u];
            if (i < QPB * ROWQ) {
                const int row = i / ROWQ;
                const int col = i - row * ROWQ;
                dstBase[(size_t)row * ROWQ + col] = v[u];
            }
        }
    }
    __syncthreads();                             // order patch after copy

    // ---- sparse patch of final state ----
    if (solver && t >= 1 && !sNotLast[q][t]) {
        float* __restrict__ orow =
            out + (size_t)BB * TT + (size_t)(bid * QPB + q) * NKC;
        orow[pk] = myVal;
    }

    // ---- counter reset for next graph replay ----
    if (tid == 0) {
        const int d = atomicAdd(&g_done, 1);
        if (d == NBLK - 1) {                     // everyone past the spin
            g_ready = 0;
            g_done  = 0;
        }
    }
}

extern "C" void kernel_launch(void* const* d_in, const int* in_sizes, int n_in,
                              void* d_out, int out_size) {
    const int*   prev_kc   = (const int*)d_in[0];
    const int*   curr_kc   = (const int*)d_in[1];
    const int*   prev_corr = (const int*)d_in[2];
    const float* kc_logits = (const float*)d_in[3];
    float*       out       = (float*)d_out;

    fused_kernel<<<NBLK, THREADS>>>(prev_kc, curr_kc, prev_corr, kc_logits, out);
}

// round 13
// speedup vs baseline: 1.3414x; 1.1026x over previous
#include <cuda_runtime.h>
#include <cuda_bf16.h>

#define NKC 5000
#define BB  512
#define TT  100
#define CCHUNK 32                       // columns per broadcast block
#define NCC ((NKC + CCHUNK - 1) / CCHUNK)   // 157 column chunks
#define NRC 4                           // row chunks (128 rows each)

__device__ float  g_c4[NKC];   // sigmoid(logits[:,4]) — default state
__device__ float4 g_p4[NKC];   // sigmoid(logits[:,0..3])

__device__ __forceinline__ float sigmoidf(float x) {
    return 1.0f / (1.0f + __expf(-x));
}

// ==== K1: column-slice broadcast (no cross-block dependency at all) ====
__global__ __launch_bounds__(256)
void bcast_kernel(const float* __restrict__ logits, float* __restrict__ out)
{
    __shared__ float sdef[CCHUNK];

    const int cc  = blockIdx.x;             // column chunk 0..156
    const int rc  = blockIdx.y;             // row chunk 0..3
    const int tid = threadIdx.x;
    const int col0 = cc * CCHUNK;

    // 32 sigmoids for this column slice (self-computed — no table, no sync)
    if (tid < CCHUNK) {
        const int k = col0 + tid;
        float v = 0.f;
        if (k < NKC) {
            v = sigmoidf(logits[k * 5 + 4]);
            if (rc == 0) {                  // publish tables for K2
                g_c4[k] = v;
                const float s0 = sigmoidf(logits[k * 5 + 0]);
                const float s1 = sigmoidf(logits[k * 5 + 1]);
                const float s2 = sigmoidf(logits[k * 5 + 2]);
                const float s3 = sigmoidf(logits[k * 5 + 3]);
                g_p4[k] = make_float4(s0, s1, s2, s3);
            }
        }
        sdef[tid] = v;
    }
    __syncthreads();

    // broadcast: 128 rows x 128 B, fully coalesced segments
    const int c4   = tid & 7;               // float4 index within chunk (0..7)
    const int rlo  = tid >> 3;              // row within 32-row group (0..31)
    const bool valid = (col0 + c4 * 4 + 3) < NKC;  // partial last chunk
    float4 val;
    val.x = sdef[c4 * 4 + 0];
    val.y = sdef[c4 * 4 + 1];
    val.z = sdef[c4 * 4 + 2];
    val.w = sdef[c4 * 4 + 3];

    float* const base = out + (size_t)BB * TT;
    #pragma unroll
    for (int rr = 0; rr < 4; rr++) {
        const int row = rc * 128 + rr * 32 + rlo;
        if (valid)
            ((float4*)(base + (size_t)row * NKC))[col0 / 4 + c4] = val;
    }
}

// ==== K2: per-batch solve (scan -> depth wavefront -> probs -> patch) ====
__global__ __launch_bounds__(128, 8)
void solve_kernel(const int* __restrict__ prev_kc,
                  const int* __restrict__ curr_kc,
                  const int* __restrict__ prev_corr,
                  float* __restrict__ out)
{
    __shared__ int   sPK[TT];
    __shared__ int   sPW[TT];
    __shared__ float sVal[TT];
    __shared__ int   sNotLast[TT];
    __shared__ int   sMaxD;

    const int b   = blockIdx.x;
    const int tid = threadIdx.x;

    float* __restrict__ orow = out + (size_t)BB * TT + (size_t)b * NKC;

    int pk = -1, ck = -1, c = 0;
    if (tid == 0) sMaxD = 0;
    if (tid < TT) {
        ck = curr_kc[b * TT + tid];
        pk = prev_kc[b * TT + tid];
        c  = prev_corr[b * TT + tid];
        sPK[tid]      = (tid >= 1) ? pk : -9;   // step 0 performs no update
        sNotLast[tid] = 0;
    }
    __syncthreads();

    // predecessor-only dependency scan (avg 12.5 int4 iters)
    int pw = -1;           // last s' <  tid writing pk  (skill source)
    int w  = -1;           // last s' <= tid writing ck  (probs source)
    if (tid < TT) {
        const int4* sp4 = (const int4*)sPK;
        const int jmax = tid >> 2;
        for (int j = 0; j <= jmax; j++) {
            const int4 v = sp4[j];
            const int s0 = 4 * j;
            if (v.x == pk && s0     < tid) pw = s0;
            if (v.y == pk && s0 + 1 < tid) pw = s0 + 1;
            if (v.z == pk && s0 + 2 < tid) pw = s0 + 2;
            if (v.w == pk && s0 + 3 < tid) pw = s0 + 3;
            if (v.x == ck && s0     <= tid) w = s0;
            if (v.y == ck && s0 + 1 <= tid) w = s0 + 1;
            if (v.z == ck && s0 + 2 <= tid) w = s0 + 2;
            if (v.w == ck && s0 + 3 <= tid) w = s0 + 3;
        }
        sPW[tid] = pw;
        if (pw >= 0) sNotLast[pw] = 1;          // pw values distinct -> plain store
    }
    __syncthreads();

    // chain depth via pointer chase (depth ~1-4)
    int depth = 0;
    if (tid >= 1 && tid < TT) {
        int j = pw;
        while (j >= 0) { j = sPW[j]; depth++; }
        atomicMax(&sMaxD, depth);
    }

    // table-dependent constants (g_p4/g_c4 ready: K1 ran before us in-stream)
    float A = 0.f, Bc = 0.f, P0 = 0.f, E = 0.f, F = 0.f, G = 0.f;
    float initSkill = 0.f, initCs = 0.f;
    if (tid < TT) {
        const float4 cp = g_p4[ck];
        G = cp.z;
        F = cp.w - cp.z;
        initCs = g_c4[ck];
        if (tid >= 1) {
            const float4 pp = g_p4[pk];
            A  = c ? pp.w : (1.0f - pp.w);      // p_out[:,1]
            Bc = c ? pp.z : (1.0f - pp.z);      // p_out[:,0]
            P0 = pp.x;
            E  = 1.0f - pp.y - pp.x;
            initSkill = g_c4[pk];
        }
    }
    __syncthreads();                            // publishes sMaxD
    const int maxD = sMaxD;

    // wavefront by depth: one barrier per round
    float myVal = 0.f;
    for (int r = 0; r <= maxD; r++) {
        if (tid >= 1 && tid < TT && depth == r) {
            const float skill = (r == 0) ? initSkill : sVal[pw];
            const float num   = A * skill;
            const float den   = fmaf(Bc, -skill, Bc) + num;  // B*(1-skill)+A*skill
            const float filt  = __fdividef(num, den);
            myVal = fmaf(E, filt, P0);
            sVal[tid] = myVal;
        }
        __syncthreads();
    }

    // probs + direct sparse patch (K1 already wrote defaults)
    if (tid < TT) {
        const float cs = (w < 0) ? initCs : sVal[w];
        out[b * TT + tid] = fmaf(F, cs, G);
        if (tid >= 1 && !sNotLast[tid])
            orow[pk] = myVal;
    }
}

extern "C" void kernel_launch(void* const* d_in, const int* in_sizes, int n_in,
                              void* d_out, int out_size) {
    const int*   prev_kc   = (const int*)d_in[0];
    const int*   curr_kc   = (const int*)d_in[1];
    const int*   prev_corr = (const int*)d_in[2];
    const float* kc_logits = (const float*)d_in[3];
    float*       out       = (float*)d_out;

    dim3 g1(NCC, NRC);
    bcast_kernel<<<g1, 256>>>(kc_logits, out);
    solve_kernel<<<BB, 128>>>(prev_kc, curr_kc, prev_corr, out);
}

// round 14
// speedup vs baseline: 1.5298x; 1.1404x over previous
#include <cuda_runtime.h>
#include <cuda_bf16.h>

#define NKC 5000
#define BB  512
#define TT  100
#define THREADS 256
#define TBL_SLICE 10   // table entries built per block (512*10 >= 5000)
#define NBUCK 128      // hash buckets for dep lookup

#define BAR_COMPUTE(n) asm volatile("bar.sync 1, %0;" :: "r"(n) : "memory")
#define BAR_COPY(n)    asm volatile("bar.sync 2, %0;" :: "r"(n) : "memory")

__device__ float  g_c4[NKC];   // sigmoid(logits[:,4]) — default state
__device__ float4 g_p4[NKC];   // sigmoid(logits[:,0..3])
__device__ int    g_ready;     // blocks that published their table slice
__device__ int    g_done;      // blocks finished (reset)

__device__ __forceinline__ float sigmoidf(float x) {
    return 1.0f / (1.0f + __expf(-x));
}

// highest step index in bucket mask (bits限 already applied) matching key, else -1
__device__ __forceinline__ int buck_find(const unsigned* m4, unsigned m0, unsigned m1,
                                         unsigned m2, unsigned m3,
                                         const int* sPK, int key) {
    unsigned w3 = m4[3] & m3, w2 = m4[2] & m2, w1 = m4[1] & m1, w0 = m4[0] & m0;
    #pragma unroll 1
    while (w3 | w2 | w1 | w0) {
        int c;
        if      (w3) { c = 96 + 31 - __clz(w3); }
        else if (w2) { c = 64 + 31 - __clz(w2); }
        else if (w1) { c = 32 + 31 - __clz(w1); }
        else         { c =      31 - __clz(w0); }
        if (sPK[c] == key) return c;
        if      (c >= 96) w3 &= ~(1u << (c - 96));
        else if (c >= 64) w2 &= ~(1u << (c - 64));
        else if (c >= 32) w1 &= ~(1u << (c - 32));
        else              w0 &= ~(1u <<  c);
    }
    return -1;
}

__global__ __launch_bounds__(THREADS, 4)
void fused_kernel(const int* __restrict__ prev_kc,
                  const int* __restrict__ curr_kc,
                  const int* __restrict__ prev_corr,
                  const float* __restrict__ logits,
                  float* __restrict__ out)
{
    __shared__ int      sPK[TT];
    __shared__ int      sPW[TT];
    __shared__ float    sVal[TT];
    __shared__ int      sNotLast[TT];
    __shared__ int      sMaxD;
    __shared__ unsigned sBuck[NBUCK][4];   // 128-bit step mask per bucket

    const int b   = blockIdx.x;
    const int tid = threadIdx.x;

    float* __restrict__ orow = out + (size_t)BB * TT + (size_t)b * NKC;

    int   pk = -1, ck = -1, c = 0;
    int   pw = -1, w = -1;
    float myVal = 0.f;

    if (tid >= 128) {
        // ================= COPY GROUP (warps 4-7) =================
        if (tid < 128 + TBL_SLICE) {
            const int k = b * TBL_SLICE + (tid - 128);
            if (k < NKC) {
                const float s0 = sigmoidf(logits[k * 5 + 0]);
                const float s1 = sigmoidf(logits[k * 5 + 1]);
                const float s2 = sigmoidf(logits[k * 5 + 2]);
                const float s3 = sigmoidf(logits[k * 5 + 3]);
                const float s4 = sigmoidf(logits[k * 5 + 4]);
                g_p4[k] = make_float4(s0, s1, s2, s3);
                g_c4[k] = s4;
            }
            __threadfence();
        }
        __syncwarp();                          // warp 4 builders done
        if (tid == 128)
            atomicAdd(&g_ready, 1);

        // clear hash buckets (warps 5-7: 96 threads x ~5-6 words of 512)
        if (tid >= 160) {
            unsigned* bw = &sBuck[0][0];
            for (int i = tid - 160; i < NBUCK * 4; i += 96)
                bw[i] = 0u;
        }

        if (tid == 160) {                      // copy-group spinner
            while (*(volatile int*)&g_ready < BB)
                __nanosleep(20);
            __threadfence();
        }
        BAR_COPY(128);

        // bulk copy with MLP=10
        {
            const float4* __restrict__ src = (const float4*)g_c4;
            float4*       __restrict__ dst = (float4*)orow;
            const int base = tid - 128;
            float4 v[10];
            #pragma unroll
            for (int u = 0; u < 10; u++) {
                const int i = base + u * 128;
                if (i < NKC / 4) v[u] = src[i];
            }
            #pragma unroll
            for (int u = 0; u < 10; u++) {
                const int i = base + u * 128;
                if (i < NKC / 4) dst[i] = v[u];
            }
        }
    } else {
        // ================= COMPUTE GROUP (warps 0-3) =================
        if (tid == 0) sMaxD = 0;
        if (tid < TT) {
            ck = curr_kc[b * TT + tid];
            pk = prev_kc[b * TT + tid];
            c  = prev_corr[b * TT + tid];
            sPK[tid]      = (tid >= 1) ? pk : -9;
            sNotLast[tid] = 0;
        }
        __syncthreads();                       // joins bucket-clear by warps 5-7

        // publish writer bits
        if (tid >= 1 && tid < TT)
            atomicOr(&sBuck[pk & (NBUCK - 1)][tid >> 5], 1u << (tid & 31));
        BAR_COMPUTE(128);

        // O(1) dependency lookups via buckets
        if (tid < TT) {
            // masks for bits < tid (pw) and bits <= tid (w)
            const int tw = tid >> 5, tb = tid & 31;
            unsigned lt[4], le[4];
            #pragma unroll
            for (int i = 0; i < 4; i++) {
                lt[i] = (i < tw) ? 0xFFFFFFFFu : (i == tw ? ((tb ? (1u << tb) : 0u) - (tb ? 1u : 0u)) : 0u);
            }
            // fix: (1u<<tb)-1 pattern without UB for tb==0
            lt[tw] = (tb == 0) ? 0u : ((1u << tb) - 1u);
            #pragma unroll
            for (int i = 0; i < 4; i++)
                le[i] = lt[i];
            le[tw] |= (1u << tb);              // include own bit for w lookup

            if (tid >= 1)
                pw = buck_find(sBuck[pk & (NBUCK - 1)], lt[0], lt[1], lt[2], lt[3], sPK, pk);
            w = buck_find(sBuck[ck & (NBUCK - 1)], le[0], le[1], le[2], le[3], sPK, ck);

            sPW[tid] = pw;
            if (pw >= 0) sNotLast[pw] = 1;     // pw values distinct -> plain store
        }
        BAR_COMPUTE(128);

        // chain depth via pointer chase (depth ~1-4)
        int depth = 0;
        if (tid >= 1 && tid < TT) {
            int j = pw;
            while (j >= 0) { j = sPW[j]; depth++; }
            atomicMax(&sMaxD, depth);
        }

        if (tid == 0) {                        // compute-group spinner
            while (*(volatile int*)&g_ready < BB)
                __nanosleep(20);
            __threadfence();
        }
        BAR_COMPUTE(128);                      // publishes sMaxD
        const int maxD = sMaxD;

        // table-dependent constants gather
        float A = 0.f, Bc = 0.f, P0 = 0.f, E = 0.f, F = 0.f, G = 0.f;
        float initSkill = 0.f, initCs = 0.f;
        if (tid < TT) {
            const float4 cp = g_p4[ck];
            G = cp.z;
            F = cp.w - cp.z;
            initCs = g_c4[ck];
            if (tid >= 1) {
                const float4 pp = g_p4[pk];
                A  = c ? pp.w : (1.0f - pp.w);
                Bc = c ? pp.z : (1.0f - pp.z);
                P0 = pp.x;
                E  = 1.0f - pp.y - pp.x;
                initSkill = g_c4[pk];
            }
        }

        // wavefront by depth
        for (int r = 0; r <= maxD; r++) {
            BAR_COMPUTE(128);
            if (tid >= 1 && tid < TT && depth == r) {
                const float skill = (r == 0) ? initSkill : sVal[pw];
                const float num   = A * skill;
                const float den   = fmaf(Bc, -skill, Bc) + num;
                const float filt  = __fdividef(num, den);
                myVal = fmaf(E, filt, P0);
                sVal[tid] = myVal;
            }
        }
        BAR_COMPUTE(128);

        // probs output
        if (tid < TT) {
            const float cs = (w < 0) ? initCs : sVal[w];
            out[b * TT + tid] = fmaf(F, cs, G);
        }
    }

    // ---- join: copy + values complete, then sparse patch ----
    __syncthreads();
    if (tid >= 1 && tid < TT && !sNotLast[tid])
        orow[pk] = myVal;

    // ---- counter reset for next graph replay ----
    if (tid == 0) {
        const int d = atomicAdd(&g_done, 1);
        if (d == BB - 1) {
            g_ready = 0;
            g_done  = 0;
        }
    }
}

extern "C" void kernel_launch(void* const* d_in, const int* in_sizes, int n_in,
                              void* d_out, int out_size) {
    const int*   prev_kc   = (const int*)d_in[0];
    const int*   curr_kc   = (const int*)d_in[1];
    const int*   prev_corr = (const int*)d_in[2];
    const float* kc_logits = (const float*)d_in[3];
    float*       out       = (float*)d_out;

    fused_kernel<<<BB, THREADS>>>(prev_kc, curr_kc, prev_corr, kc_logits, out);
}

// round 15
// speedup vs baseline: 2.1463x; 1.4030x over previous
#include <cuda_runtime.h>
#include <cuda_bf16.h>

#define NKC 5000
#define BB  512
#define TT  100
#define THREADS 256
#define TBL_SLICE 10   // g_c4 entries built per block (512*10 >= 5000)

#define BAR_COMPUTE(n) asm volatile("bar.sync 1, %0;" :: "r"(n) : "memory")
#define BAR_COPY(n)    asm volatile("bar.sync 2, %0;" :: "r"(n) : "memory")

__device__ float g_c4[NKC];    // sigmoid(logits[:,4]) — default state
__device__ int   g_ready;     // blocks that published their table slice
__device__ int   g_done;      // blocks finished (reset)

// sigmoid via single-MUFU tanh.approx: s = 0.5 + 0.5*tanh(x/2)
__device__ __forceinline__ float sigmoidf(float x) {
    float t;
    asm("tanh.approx.f32 %0, %1;" : "=f"(t) : "f"(0.5f * x));
    return fmaf(0.5f, t, 0.5f);
}

__global__ __launch_bounds__(THREADS, 4)
void fused_kernel(const int* __restrict__ prev_kc,
                  const int* __restrict__ curr_kc,
                  const int* __restrict__ prev_corr,
                  const float* __restrict__ logits,
                  float* __restrict__ out)
{
    __shared__ int   sPK[TT];
    __shared__ int   sPW[TT];
    __shared__ float sVal[TT];
    __shared__ int   sNotLast[TT];
    __shared__ int   sMaxD;

    const int b   = blockIdx.x;
    const int tid = threadIdx.x;

    float* __restrict__ orow = out + (size_t)BB * TT + (size_t)b * NKC;

    int   pk = -1, ck = -1, c = 0;
    float myVal = 0.f;

    if (tid >= 128) {
        // ================= COPY GROUP (warps 4-7) =================
        // build g_c4 slice -> arrive -> spin -> stream copy. No solver coupling.
        if (tid < 128 + TBL_SLICE) {
            const int k = b * TBL_SLICE + (tid - 128);
            if (k < NKC)
                g_c4[k] = sigmoidf(logits[k * 5 + 4]);
            __threadfence();
        }
        __syncwarp();                          // warp 4: builders done
        if (tid == 128)
            atomicAdd(&g_ready, 1);

        if (tid == 160) {                      // copy-group spinner (warp 5)
            while (*(volatile int*)&g_ready < BB)
                __nanosleep(20);
            __threadfence();
        }
        BAR_COPY(128);

        // bulk copy with MLP=10: all loads issued before any store
        {
            const float4* __restrict__ src = (const float4*)g_c4;
            float4*       __restrict__ dst = (float4*)orow;
            const int base = tid - 128;
            float4 v[10];
            #pragma unroll
            for (int u = 0; u < 10; u++) {
                const int i = base + u * 128;
                if (i < NKC / 4) v[u] = src[i];
            }
            #pragma unroll
            for (int u = 0; u < 10; u++) {
                const int i = base + u * 128;
                if (i < NKC / 4) dst[i] = v[u];
            }
        }
    } else {
        // ================= SOLVER GROUP (warps 0-3) =================
        // fully independent: inline sigmoids, no table, no global spin.
        if (tid == 0) sMaxD = 0;
        if (tid < TT) {
            ck = curr_kc[b * TT + tid];
            pk = prev_kc[b * TT + tid];
            c  = prev_corr[b * TT + tid];
            sPK[tid]      = (tid >= 1) ? pk : -9;   // step 0 performs no update
            sNotLast[tid] = 0;
        }
        BAR_COMPUTE(128);

        // predecessor-only dependency scan (avg 12.5 int4 iters)
        int pw = -1, w = -1;
        if (tid < TT) {
            const int4* sp4 = (const int4*)sPK;
            const int jmax = tid >> 2;
            for (int j = 0; j <= jmax; j++) {
                const int4 v = sp4[j];
                const int s0 = 4 * j;
                if (v.x == pk && s0     < tid) pw = s0;
                if (v.y == pk && s0 + 1 < tid) pw = s0 + 1;
                if (v.z == pk && s0 + 2 < tid) pw = s0 + 2;
                if (v.w == pk && s0 + 3 < tid) pw = s0 + 3;
                if (v.x == ck && s0     <= tid) w = s0;
                if (v.y == ck && s0 + 1 <= tid) w = s0 + 1;
                if (v.z == ck && s0 + 2 <= tid) w = s0 + 2;
                if (v.w == ck && s0 + 3 <= tid) w = s0 + 3;
            }
            sPW[tid] = pw;
            if (pw >= 0) sNotLast[pw] = 1;     // pw values distinct -> plain store
        }
        BAR_COMPUTE(128);

        // chain depth via pointer chase (depth ~1-4)
        int depth = 0;
        if (tid >= 1 && tid < TT) {
            int j = pw;
            while (j >= 0) { j = sPW[j]; depth++; }
            atomicMax(&sMaxD, depth);
        }

        // inline constants (8 MUFU tanh per thread, overlapped with chase)
        float A = 0.f, Bc = 0.f, P0 = 0.f, E = 0.f, F = 0.f, G = 0.f;
        float initSkill = 0.f, initCs = 0.f;
        if (tid < TT) {
            const float c2 = sigmoidf(logits[ck * 5 + 2]);
            const float c3 = sigmoidf(logits[ck * 5 + 3]);
            G = c2;
            F = c3 - c2;
            initCs = sigmoidf(logits[ck * 5 + 4]);
            if (tid >= 1) {
                const float p0 = sigmoidf(logits[pk * 5 + 0]);
                const float p1 = sigmoidf(logits[pk * 5 + 1]);
                const float p2 = sigmoidf(logits[pk * 5 + 2]);
                const float p3 = sigmoidf(logits[pk * 5 + 3]);
                A  = c ? p3 : (1.0f - p3);     // p_out[:,1]
                Bc = c ? p2 : (1.0f - p2);     // p_out[:,0]
                P0 = p0;
                E  = 1.0f - p1 - p0;
                initSkill = sigmoidf(logits[pk * 5 + 4]);
            }
        }
        BAR_COMPUTE(128);                      // publishes sMaxD
        const int maxD = sMaxD;

        // wavefront by depth: one group barrier per round
        for (int r = 0; r <= maxD; r++) {
            if (tid >= 1 && tid < TT && depth == r) {
                const float skill = (r == 0) ? initSkill : sVal[pw];
                const float num   = A * skill;
                const float den   = fmaf(Bc, -skill, Bc) + num;  // B*(1-skill)+A*skill
                const float filt  = __fdividef(num, den);
                myVal = fmaf(E, filt, P0);
                sVal[tid] = myVal;
            }
            BAR_COMPUTE(128);
        }

        // probs output
        if (tid < TT) {
            const float cs = (w < 0) ? initCs : sVal[w];
            out[b * TT + tid] = fmaf(F, cs, G);
        }
    }

    // ---- join: copy complete + values complete, then sparse patch ----
    __syncthreads();
    if (tid >= 1 && tid < TT && !sNotLast[tid])
        orow[pk] = myVal;

    // ---- counter reset for next graph replay ----
    if (tid == 0) {
        const int d = atomicAdd(&g_done, 1);
        if (d == BB - 1) {          // last block: everyone has passed the spin
            g_ready = 0;
            g_done  = 0;
        }
    }
}

extern "C" void kernel_launch(void* const* d_in, const int* in_sizes, int n_in,
                              void* d_out, int out_size) {
    const int*   prev_kc   = (const int*)d_in[0];
    const int*   curr_kc   = (const int*)d_in[1];
    const int*   prev_corr = (const int*)d_in[2];
    const float* kc_logits = (const float*)d_in[3];
    float*       out       = (float*)d_out;

    fused_kernel<<<BB, THREADS>>>(prev_kc, curr_kc, prev_corr, kc_logits, out);
}